// round 3
// baseline (speedup 1.0000x reference)
#include <cuda_runtime.h>
#include <cuda_bf16.h>

// Entmax15: out = clip(X - tau*, 0)^2 with sum(out) = 1 per row,
// X = (masked_scores - rowmax) * 0.5.
//
// tau* via exact piecewise-quadratic (Michelot-style) iteration: on the
// current support A = {x > tau}, f(t) = sum_A (x - t)^2 is exactly quadratic;
// jump to its root each step. Support shrinks monotonically from the left;
// terminate when the support size repeats (then tau is exact). ~4-5 iters.
//
// Per-iteration cost kept minimal (the R2 lesson): 10 shuffles (S1,S2 only),
// support count via ballot+popc (ALU pipe), block combine serialized in
// tid==0 (8 LDS.128 per block, not per thread), 2 barriers.

constexpr int S_LEN   = 2048;
constexpr int THREADS = 256;
constexpr int WARPS   = THREADS / 32;
constexpr float NEG_FILL = -1e4f;

__global__ void __launch_bounds__(THREADS, 6)
entmax15_kernel(const float* __restrict__ scores,
                const int*   __restrict__ mask,
                float*       __restrict__ out)
{
    const long long base = (long long)blockIdx.x * S_LEN;
    const float4* s4 = reinterpret_cast<const float4*>(scores + base);
    const int4*   m4 = reinterpret_cast<const int4*>(mask + base);
    float4*       o4 = reinterpret_cast<float4*>(out + base);

    const int tid  = threadIdx.x;
    const int warp = tid >> 5;
    const int lane = tid & 31;

    // ---- load 8 elems/thread, apply mask ----
    float4 a = s4[tid];
    float4 b = s4[tid + THREADS];
    int4  ma = m4[tid];
    int4  mb = m4[tid + THREADS];

    float x[8];
    x[0] = ma.x ? a.x : NEG_FILL;
    x[1] = ma.y ? a.y : NEG_FILL;
    x[2] = ma.z ? a.z : NEG_FILL;
    x[3] = ma.w ? a.w : NEG_FILL;
    x[4] = mb.x ? b.x : NEG_FILL;
    x[5] = mb.y ? b.y : NEG_FILL;
    x[6] = mb.z ? b.z : NEG_FILL;
    x[7] = mb.w ? b.w : NEG_FILL;

    __shared__ float4 red[WARPS];     // (k, S1, S2, -) per warp
    __shared__ float  sh_bcast[2];    // (tau, done)

    // ---- block max ----
    float mx = x[0];
    #pragma unroll
    for (int i = 1; i < 8; ++i) mx = fmaxf(mx, x[i]);
    #pragma unroll
    for (int o = 16; o; o >>= 1) mx = fmaxf(mx, __shfl_xor_sync(0xffffffffu, mx, o));
    if (lane == 0) red[warp].x = mx;
    __syncthreads();
    if (tid == 0) {
        float v = red[0].x;
        #pragma unroll
        for (int w = 1; w < WARPS; ++w) v = fmaxf(v, red[w].x);
        sh_bcast[0] = v;
    }
    __syncthreads();
    mx = sh_bcast[0];

    // ---- alpha=1.5 transform: X = (x - max) * 0.5 so max(X) == 0 ----
    const float mxh = mx * 0.5f;
    #pragma unroll
    for (int i = 0; i < 8; ++i) x[i] = fmaf(x[i], 0.5f, -mxh);

    // ---- exact piecewise-quadratic root find; tau* in [-1, 0) ----
    float tau = -1.0f;   // max element alone contributes 1 => f(-1) >= 1

    #pragma unroll 1
    for (int it = 0; it < 24; ++it) {
        float s1 = 0.0f, s2 = 0.0f;
        int   k  = 0;
        #pragma unroll
        for (int i = 0; i < 8; ++i) {
            float d  = x[i] - tau;
            float dc = fmaxf(d, 0.0f);
            s1 += dc;
            s2  = fmaf(dc, dc, s2);
            k  += __popc(__ballot_sync(0xffffffffu, d > 0.0f));  // warp-wide count
        }
        #pragma unroll
        for (int o = 16; o; o >>= 1) {
            s1 += __shfl_xor_sync(0xffffffffu, s1, o);
            s2 += __shfl_xor_sync(0xffffffffu, s2, o);
        }
        if (lane == 0) red[warp] = make_float4((float)k, s1, s2, 0.0f);
        __syncthreads();
        if (tid == 0) {
            float K = 0.0f, S1 = 0.0f, S2 = 0.0f;
            #pragma unroll
            for (int w = 0; w < WARPS; ++w) {
                float4 r = red[w];
                K += r.x; S1 += r.y; S2 += r.z;
            }
            // root of K*dlt^2 - 2*S1*dlt + (S2 - 1) = 0 (smaller root)
            float disc = fmaxf(fmaf(-K, S2 - 1.0f, S1 * S1), 0.0f);
            float dlt  = (S1 - sqrtf(disc)) / K;
            sh_bcast[0] = tau + dlt;
            // same support as last iter => jump was exact => done
            sh_bcast[1] = (K == red[0].w || dlt == 0.0f) ? 1.0f : 0.0f;
            red[0].w = K;   // stash prev support size (survives iterations)
        }
        __syncthreads();
        tau = sh_bcast[0];
        if (sh_bcast[1] != 0.0f) break;
    }

    // ---- emit p = clip(X - tau, 0)^2 ----
    float4 r0, r1;
    float d;
    d = fmaxf(x[0] - tau, 0.0f); r0.x = d * d;
    d = fmaxf(x[1] - tau, 0.0f); r0.y = d * d;
    d = fmaxf(x[2] - tau, 0.0f); r0.z = d * d;
    d = fmaxf(x[3] - tau, 0.0f); r0.w = d * d;
    d = fmaxf(x[4] - tau, 0.0f); r1.x = d * d;
    d = fmaxf(x[5] - tau, 0.0f); r1.y = d * d;
    d = fmaxf(x[6] - tau, 0.0f); r1.z = d * d;
    d = fmaxf(x[7] - tau, 0.0f); r1.w = d * d;
    o4[tid]           = r0;
    o4[tid + THREADS] = r1;
}

extern "C" void kernel_launch(void* const* d_in, const int* in_sizes, int n_in,
                              void* d_out, int out_size)
{
    const float* scores = (const float*)d_in[0];
    const int*   mask   = (const int*)d_in[1];
    float*       out    = (float*)d_out;
    const int rows = in_sizes[0] / S_LEN;
    entmax15_kernel<<<rows, THREADS>>>(scores, mask, out);
}

// round 4
// speedup vs baseline: 3.6208x; 3.6208x over previous
#include <cuda_runtime.h>
#include <cuda_bf16.h>

// Entmax15: out = clip(X - tau*, 0)^2 with sum(out) = 1 per row,
// X = (masked_scores - rowmax) * 0.5.
//
// tau* via exact piecewise-quadratic (Michelot) iteration: on the current
// support A = {x > tau}, f(t) = sum_A (x - t)^2 is exactly quadratic; jump to
// its root. tau increases monotonically, support shrinks monotonically;
// when the support size repeats the jump is exact -> terminate. ~4-5 iters.
//
// Cost discipline (R2/R3 lessons): 10 shuffles per iter (S1,S2 only),
// support count via per-thread int adds + one REDUX.SUM, block combine
// serialized in tid==0, prev-K in a dedicated smem word (R3 bug fix).
// 128 threads x 16 elems/thread halves per-row shuffle/barrier totals vs 256.

constexpr int S_LEN   = 2048;
constexpr int THREADS = 128;
constexpr int WARPS   = THREADS / 32;
constexpr int EPT     = S_LEN / THREADS;      // 16 elems per thread
constexpr int V4      = EPT / 4;              // 4 float4 per thread
constexpr float NEG_FILL = -1e4f;

__global__ void __launch_bounds__(THREADS, 8)
entmax15_kernel(const float* __restrict__ scores,
                const int*   __restrict__ mask,
                float*       __restrict__ out)
{
    const long long base = (long long)blockIdx.x * S_LEN;
    const float4* s4 = reinterpret_cast<const float4*>(scores + base);
    const int4*   m4 = reinterpret_cast<const int4*>(mask + base);
    float4*       o4 = reinterpret_cast<float4*>(out + base);

    const int tid  = threadIdx.x;
    const int warp = tid >> 5;
    const int lane = tid & 31;

    // ---- load 16 elems/thread, apply mask ----
    float x[EPT];
    #pragma unroll
    for (int v = 0; v < V4; ++v) {
        float4 a = s4[tid + v * THREADS];
        int4   m = m4[tid + v * THREADS];
        x[v * 4 + 0] = m.x ? a.x : NEG_FILL;
        x[v * 4 + 1] = m.y ? a.y : NEG_FILL;
        x[v * 4 + 2] = m.z ? a.z : NEG_FILL;
        x[v * 4 + 3] = m.w ? a.w : NEG_FILL;
    }

    __shared__ float4 red[WARPS];    // (K, S1, S2, -) per warp
    __shared__ float  sh_bcast[2];   // (tau, done)
    __shared__ float  sh_prevK;      // dedicated prev-support stash (tid==0 only)

    // ---- block max ----
    float mx = x[0];
    #pragma unroll
    for (int i = 1; i < EPT; ++i) mx = fmaxf(mx, x[i]);
    #pragma unroll
    for (int o = 16; o; o >>= 1) mx = fmaxf(mx, __shfl_xor_sync(0xffffffffu, mx, o));
    if (lane == 0) red[warp].x = mx;
    __syncthreads();
    if (tid == 0) {
        float v = red[0].x;
        #pragma unroll
        for (int w = 1; w < WARPS; ++w) v = fmaxf(v, red[w].x);
        sh_bcast[0] = v;
        sh_prevK    = -1.0f;
    }
    __syncthreads();
    mx = sh_bcast[0];

    // ---- alpha=1.5 transform: X = (x - max) * 0.5 so max(X) == 0 ----
    const float mxh = mx * 0.5f;
    #pragma unroll
    for (int i = 0; i < EPT; ++i) x[i] = fmaf(x[i], 0.5f, -mxh);

    // ---- exact piecewise-quadratic root find; tau* in [-1, 0) ----
    float tau = -1.0f;   // the max element alone contributes 1 => f(-1) >= 1

    #pragma unroll 1
    for (int it = 0; it < 24; ++it) {
        float s1 = 0.0f, s2 = 0.0f;
        int   k  = 0;
        #pragma unroll
        for (int i = 0; i < EPT; ++i) {
            float d  = x[i] - tau;
            float dc = fmaxf(d, 0.0f);
            s1 += dc;
            s2  = fmaf(dc, dc, s2);
            k  += (d > 0.0f);
        }
        #pragma unroll
        for (int o = 16; o; o >>= 1) {
            s1 += __shfl_xor_sync(0xffffffffu, s1, o);
            s2 += __shfl_xor_sync(0xffffffffu, s2, o);
        }
        k = __reduce_add_sync(0xffffffffu, k);   // single REDUX.SUM
        if (lane == 0) red[warp] = make_float4((float)k, s1, s2, 0.0f);
        __syncthreads();
        if (tid == 0) {
            float K = 0.0f, S1 = 0.0f, S2 = 0.0f;
            #pragma unroll
            for (int w = 0; w < WARPS; ++w) {
                float4 r = red[w];
                K += r.x; S1 += r.y; S2 += r.z;
            }
            // smaller root of K*dlt^2 - 2*S1*dlt + (S2 - 1) = 0
            float disc = fmaxf(fmaf(-K, S2 - 1.0f, S1 * S1), 0.0f);
            float dlt  = (S1 - sqrtf(disc)) / K;
            sh_bcast[0] = tau + dlt;
            sh_bcast[1] = (K == sh_prevK) ? 1.0f : 0.0f;  // support repeated -> exact
            sh_prevK    = K;
        }
        __syncthreads();
        tau = sh_bcast[0];
        if (sh_bcast[1] != 0.0f) break;
    }

    // ---- emit p = clip(X - tau, 0)^2 ----
    #pragma unroll
    for (int v = 0; v < V4; ++v) {
        float4 r;
        float d;
        d = fmaxf(x[v * 4 + 0] - tau, 0.0f); r.x = d * d;
        d = fmaxf(x[v * 4 + 1] - tau, 0.0f); r.y = d * d;
        d = fmaxf(x[v * 4 + 2] - tau, 0.0f); r.z = d * d;
        d = fmaxf(x[v * 4 + 3] - tau, 0.0f); r.w = d * d;
        o4[tid + v * THREADS] = r;
    }
}

extern "C" void kernel_launch(void* const* d_in, const int* in_sizes, int n_in,
                              void* d_out, int out_size)
{
    const float* scores = (const float*)d_in[0];
    const int*   mask   = (const int*)d_in[1];
    float*       out    = (float*)d_out;
    const int rows = in_sizes[0] / S_LEN;
    entmax15_kernel<<<rows, THREADS>>>(scores, mask, out);
}

// round 6
// speedup vs baseline: 4.1880x; 1.1566x over previous
#include <cuda_runtime.h>
#include <cuda_bf16.h>

// Entmax15: out = clip(X - tau*, 0)^2 with sum(out) = 1 per row,
// X = (masked_scores - rowmax) * 0.5.
//
// tau* via Newton on g(tau) = sqrt(f(tau)) - 1, f(tau) = sum max(X-tau,0)^2.
// On each fixed-support piece f = K(t-c)^2 + v, so g is a convex hyperbola
// branch (2 f f'' - f'^2 = 4Kv >= 0); g' continuous and nondecreasing across
// pieces => g convex left of the root => Newton from tau=-1 is monotone and
// never overshoots. Step: dlt = (S2 - sqrt(S2)) / S1 with
// S1 = sum max(d,0), S2 = sum max(d,0)^2 — no support count needed.
//
// NOTE: redux.sync.f32 is NOT available on sm_103a (R5 ptxas failure) —
// warp reduces are shuffle trees. Block combine serialized in tid==0
// (minimum total instructions, per R2/R3 measurements).

constexpr int S_LEN   = 2048;
constexpr int THREADS = 128;
constexpr int WARPS   = THREADS / 32;
constexpr int EPT     = S_LEN / THREADS;      // 16 elems per thread
constexpr int V4      = EPT / 4;              // 4 float4 per thread
constexpr float NEG_FILL = -1e4f;

__global__ void __launch_bounds__(THREADS, 8)
entmax15_kernel(const float* __restrict__ scores,
                const int*   __restrict__ mask,
                float*       __restrict__ out)
{
    const long long base = (long long)blockIdx.x * S_LEN;
    const float4* s4 = reinterpret_cast<const float4*>(scores + base);
    const int4*   m4 = reinterpret_cast<const int4*>(mask + base);
    float4*       o4 = reinterpret_cast<float4*>(out + base);

    const int tid  = threadIdx.x;
    const int warp = tid >> 5;
    const int lane = tid & 31;

    // ---- load 16 elems/thread, apply mask ----
    float x[EPT];
    #pragma unroll
    for (int v = 0; v < V4; ++v) {
        float4 a = s4[tid + v * THREADS];
        int4   m = m4[tid + v * THREADS];
        x[v * 4 + 0] = m.x ? a.x : NEG_FILL;
        x[v * 4 + 1] = m.y ? a.y : NEG_FILL;
        x[v * 4 + 2] = m.z ? a.z : NEG_FILL;
        x[v * 4 + 3] = m.w ? a.w : NEG_FILL;
    }

    __shared__ float2 red[WARPS];    // (S1, S2) per warp
    __shared__ float  sh_bcast[2];   // (tau / max, done)

    // ---- block max ----
    float mx = x[0];
    #pragma unroll
    for (int i = 1; i < EPT; ++i) mx = fmaxf(mx, x[i]);
    #pragma unroll
    for (int o = 16; o; o >>= 1) mx = fmaxf(mx, __shfl_xor_sync(0xffffffffu, mx, o));
    if (lane == 0) red[warp].x = mx;
    __syncthreads();
    if (tid == 0) {
        float v = red[0].x;
        #pragma unroll
        for (int w = 1; w < WARPS; ++w) v = fmaxf(v, red[w].x);
        sh_bcast[0] = v;
    }
    __syncthreads();
    mx = sh_bcast[0];

    // ---- alpha=1.5 transform: X = (x - max) * 0.5 so max(X) == 0 ----
    const float mxh = mx * 0.5f;
    #pragma unroll
    for (int i = 0; i < EPT; ++i) x[i] = fmaf(x[i], 0.5f, -mxh);

    // ---- Newton-on-sqrt root find; tau* in [-1, 0) ----
    float tau = -1.0f;   // the max element alone contributes 1 => f(-1) >= 1

    #pragma unroll 1
    for (int it = 0; it < 20; ++it) {
        float s1a = 0.0f, s1b = 0.0f, s2a = 0.0f, s2b = 0.0f;
        #pragma unroll
        for (int i = 0; i < EPT; i += 2) {
            float d0 = fmaxf(x[i]     - tau, 0.0f);
            float d1 = fmaxf(x[i + 1] - tau, 0.0f);
            s1a += d0;                s1b += d1;
            s2a  = fmaf(d0, d0, s2a); s2b  = fmaf(d1, d1, s2b);
        }
        float s1 = s1a + s1b;
        float s2 = s2a + s2b;
        #pragma unroll
        for (int o = 16; o; o >>= 1) {
            s1 += __shfl_xor_sync(0xffffffffu, s1, o);
            s2 += __shfl_xor_sync(0xffffffffu, s2, o);
        }
        if (lane == 0) red[warp] = make_float2(s1, s2);
        __syncthreads();
        if (tid == 0) {
            float S1 = 0.0f, S2 = 0.0f;
            #pragma unroll
            for (int w = 0; w < WARPS; ++w) {
                float2 r = red[w];
                S1 += r.x; S2 += r.y;
            }
            // Newton on sqrt(f)-1: dlt = (f - sqrt(f)) / f' ... = (S2 - sqrt(S2)) / S1
            float dlt = (S2 - sqrtf(S2)) / fmaxf(S1, 1e-20f);
            sh_bcast[0] = tau + dlt;
            sh_bcast[1] = (dlt < 1e-6f) ? 1.0f : 0.0f;
        }
        __syncthreads();
        tau = sh_bcast[0];
        if (sh_bcast[1] != 0.0f) break;
    }

    // ---- emit p = clip(X - tau, 0)^2 ----
    #pragma unroll
    for (int v = 0; v < V4; ++v) {
        float4 r;
        float d;
        d = fmaxf(x[v * 4 + 0] - tau, 0.0f); r.x = d * d;
        d = fmaxf(x[v * 4 + 1] - tau, 0.0f); r.y = d * d;
        d = fmaxf(x[v * 4 + 2] - tau, 0.0f); r.z = d * d;
        d = fmaxf(x[v * 4 + 3] - tau, 0.0f); r.w = d * d;
        o4[tid + v * THREADS] = r;
    }
}

extern "C" void kernel_launch(void* const* d_in, const int* in_sizes, int n_in,
                              void* d_out, int out_size)
{
    const float* scores = (const float*)d_in[0];
    const int*   mask   = (const int*)d_in[1];
    float*       out    = (float*)d_out;
    const int rows = in_sizes[0] / S_LEN;
    entmax15_kernel<<<rows, THREADS>>>(scores, mask, out);
}